// round 7
// baseline (speedup 1.0000x reference)
#include <cuda_runtime.h>
#include <math.h>

// ---------------- problem constants ----------------
#define NB 32
#define NC 256
#define NH 64
#define NW 64
// MIP=8, HID=256, OUT=14

// ---------------- scratch ----------------
__device__ float g_y0[NB * NC * 128];   // [b][c][0..63]=row means, [64..127]=col means
__device__ float g_ys[NB * 8 * 128];    // hswish(bn(w1@y0))
__device__ float g_att[NB * NC * 128];  // [b][c][0..63]=a_h, [64..127]=a_w
__device__ float g_p[NB * NC];          // pooled features
__device__ float g_hdd[NB * 256];       // FC1 activations

// ================= K1: row & column means of x (single pass) =================
__global__ void k_means(const float* __restrict__ x) {
    int bc = blockIdx.x;
    const float* xp = x + (size_t)bc * (NH * NW);
    int tid = threadIdx.x;
    int seg = tid & 15, rsub = tid >> 4;

    __shared__ float rowsum[64];
    __shared__ float cred[16][68];

    float c0 = 0.f, c1 = 0.f, c2 = 0.f, c3 = 0.f;
#pragma unroll
    for (int it = 0; it < 4; it++) {
        int row = it * 16 + rsub;
        float4 v = __ldg((const float4*)(xp + row * NW) + seg);
        float rs = v.x + v.y + v.z + v.w;
#pragma unroll
        for (int o = 8; o; o >>= 1) rs += __shfl_xor_sync(0xffffffffu, rs, o, 16);
        if (seg == 0) rowsum[row] = rs;
        c0 += v.x; c1 += v.y; c2 += v.z; c3 += v.w;
    }
    cred[rsub][4 * seg + 0] = c0;
    cred[rsub][4 * seg + 1] = c1;
    cred[rsub][4 * seg + 2] = c2;
    cred[rsub][4 * seg + 3] = c3;
    __syncthreads();

    if (tid < 64) {
        float cs = 0.f;
#pragma unroll
        for (int r = 0; r < 16; r++) cs += cred[r][tid];
        float* yo = g_y0 + (size_t)bc * 128;
        yo[tid]      = rowsum[tid] * (1.f / 64.f);
        yo[64 + tid] = cs * (1.f / 64.f);
    }
}

// ================= K2a: y = hswish(bn(w1 @ y0)) =================
// grid (NB, 4): b, l-tile. 256 threads = 8 m x 32 l.
// Batch-unrolled 16 with 4 independent accumulators for MLP.
__global__ void k_att1(const float* __restrict__ ca_w1,
                       const float* __restrict__ bng, const float* __restrict__ bnb,
                       const float* __restrict__ bnm, const float* __restrict__ bnv) {
    int b = blockIdx.x, lt = blockIdx.y;
    int tid = threadIdx.x;
    int lsub = tid & 31, m = tid >> 5;
    int l = lt * 32 + lsub;

    const float* y0b = g_y0 + (size_t)b * NC * 128 + l;
    const float* w1m = ca_w1 + m * NC;

    float a0 = 0.f, a1 = 0.f, a2 = 0.f, a3 = 0.f;
    for (int c0 = 0; c0 < NC; c0 += 16) {
        float wv[16], vv[16];
#pragma unroll
        for (int i = 0; i < 16; i++) wv[i] = __ldg(w1m + c0 + i);
#pragma unroll
        for (int i = 0; i < 16; i++) vv[i] = __ldg(y0b + (c0 + i) * 128);
#pragma unroll
        for (int i = 0; i < 16; i += 4) {
            a0 = fmaf(wv[i + 0], vv[i + 0], a0);
            a1 = fmaf(wv[i + 1], vv[i + 1], a1);
            a2 = fmaf(wv[i + 2], vv[i + 2], a2);
            a3 = fmaf(wv[i + 3], vv[i + 3], a3);
        }
    }
    float acc = (a0 + a1) + (a2 + a3);

    float sc = __ldg(bng + m) * rsqrtf(__ldg(bnv + m) + 1e-5f);
    float yb = (acc - __ldg(bnm + m)) * sc + __ldg(bnb + m);
    float hs = yb * fminf(fmaxf(yb + 3.f, 0.f), 6.f) * (1.f / 6.f);
    g_ys[((size_t)b * 8 + m) * 128 + l] = hs;
}

// ================= K2b: attention maps =================
// grid (NB, 8): b, cg (32-channel group). 256 threads.
__global__ void k_att2(const float* __restrict__ ca_wh, const float* __restrict__ ca_ww) {
    __shared__ float ys[8 * 128];
    int b = blockIdx.x, cg = blockIdx.y;
    int tid = threadIdx.x;

    ((float4*)ys)[tid] = __ldg((const float4*)(g_ys + (size_t)b * 8 * 128) + tid);
    __syncthreads();

    int c = cg * 32 + (tid >> 3);
    int l0 = (tid & 7) * 16;
    bool ish = (l0 < 64);
    float wv[8];
#pragma unroll
    for (int m = 0; m < 8; m++)
        wv[m] = ish ? __ldg(ca_wh + c * 8 + m) : __ldg(ca_ww + c * 8 + m);

    float o16[16];
#pragma unroll
    for (int i = 0; i < 16; i++) {
        int l = l0 + i;
        float s = 0.f;
#pragma unroll
        for (int m = 0; m < 8; m++) s = fmaf(wv[m], ys[m * 128 + l], s);
        o16[i] = 1.f / (1.f + expf(-s));
    }
    float* ap = g_att + (size_t)b * NC * 128 + (size_t)c * 128 + l0;
#pragma unroll
    for (int i = 0; i < 4; i++)
        *(float4*)(ap + 4 * i) = make_float4(o16[4*i], o16[4*i+1], o16[4*i+2], o16[4*i+3]);
}

// ================= K3: attention-weighted pooling (zero prologue) =================
__global__ void k_pool(const float* __restrict__ x) {
    int bc = blockIdx.x;
    const float* xp = x + (size_t)bc * (NH * NW);
    int tid = threadIdx.x, lane = tid & 31, wp = tid >> 5;

    __shared__ float ah[64], aw[64];
    __shared__ float ws[8];

    if (tid < 128) {
        float a = g_att[(size_t)bc * 128 + tid];
        if (tid < 64) ah[tid] = a; else aw[tid - 64] = a;
    }
    __syncthreads();

    int seg = tid & 15, rsub = tid >> 4;
    float aw0 = aw[4 * seg + 0], aw1 = aw[4 * seg + 1];
    float aw2 = aw[4 * seg + 2], aw3 = aw[4 * seg + 3];

    float acc = 0.f;
#pragma unroll
    for (int it = 0; it < 4; it++) {
        int row = it * 16 + rsub;
        float4 v = __ldg((const float4*)(xp + row * NW) + seg);
        float rdot = fmaf(v.x, aw0, fmaf(v.y, aw1, fmaf(v.z, aw2, v.w * aw3)));
        acc = fmaf(ah[row], rdot, acc);
    }
#pragma unroll
    for (int o = 16; o; o >>= 1) acc += __shfl_xor_sync(0xffffffffu, acc, o);
    if (lane == 0) ws[wp] = acc;
    __syncthreads();
    if (tid == 0) {
        float s = 0.f;
#pragma unroll
        for (int w = 0; w < 8; w++) s += ws[w];
        g_p[bc] = s * (1.f / 4096.f);
    }
}

// ================= K4a: FC1 + BN + ReLU (prefetched weights) =================
// grid (NB, 8): b, jg. warp wp handles rows j = jg*32 + wp*4 + jo.
__global__ void k_fc1(const float* __restrict__ fc1_w, const float* __restrict__ fc1_b,
                      const float* __restrict__ bn1_g, const float* __restrict__ bn1_b,
                      const float* __restrict__ bn1_m, const float* __restrict__ bn1_v) {
    int b = blockIdx.x, jg = blockIdx.y;
    int tid = threadIdx.x, lane = tid & 31, wp = tid >> 5;

    __shared__ float ps[256];
    ps[tid] = g_p[b * NC + tid];
    __syncthreads();

    const float* pl = ps + lane * 8;
    int jbase = jg * 32 + wp * 4;

    // prefetch all 8 float4 weight loads (4 rows x 2) -> MLP 8
    float4 A[4][2];
#pragma unroll
    for (int jo = 0; jo < 4; jo++) {
        const float4* wr = (const float4*)(fc1_w + (jbase + jo) * 256);
        A[jo][0] = __ldg(wr + lane * 2);
        A[jo][1] = __ldg(wr + lane * 2 + 1);
    }

#pragma unroll
    for (int jo = 0; jo < 4; jo++) {
        int j = jbase + jo;
        float4 a0 = A[jo][0], a1 = A[jo][1];
        float acc = a0.x * pl[0] + a0.y * pl[1] + a0.z * pl[2] + a0.w * pl[3]
                  + a1.x * pl[4] + a1.y * pl[5] + a1.z * pl[6] + a1.w * pl[7];
#pragma unroll
        for (int o = 16; o; o >>= 1) acc += __shfl_xor_sync(0xffffffffu, acc, o);
        if (lane == 0) {
            float v = acc + __ldg(fc1_b + j);
            v = (v - __ldg(bn1_m + j)) * (__ldg(bn1_g + j) * rsqrtf(__ldg(bn1_v + j) + 1e-5f))
                + __ldg(bn1_b + j);
            g_hdd[b * 256 + j] = fmaxf(v, 0.f);
        }
    }
}

// ================= geometry helpers =================
__device__ __forceinline__ float softplus_f(float x) {
    return fmaxf(x, 0.f) + log1pf(expf(-fabsf(x)));
}

// LAPACK slaev2, bit-faithful.
__device__ void slaev2(float a, float b, float c,
                       float& rt1, float& rt2, float& cs1, float& sn1) {
    float sm = a + c, df = a - c, adf = fabsf(df);
    float tb = b + b, ab = fabsf(tb);
    float acmx, acmn;
    if (fabsf(a) > fabsf(c)) { acmx = a; acmn = c; } else { acmx = c; acmn = a; }
    float rt;
    if (adf > ab)      { float r = ab / adf; rt = adf * sqrtf(1.f + r * r); }
    else if (adf < ab) { float r = adf / ab; rt = ab * sqrtf(1.f + r * r); }
    else               { rt = ab * sqrtf(2.f); }
    int sgn1;
    if (sm < 0.f)      { rt1 = 0.5f * (sm - rt); sgn1 = -1; rt2 = (acmx / rt1) * acmn - (b / rt1) * b; }
    else if (sm > 0.f) { rt1 = 0.5f * (sm + rt); sgn1 = 1;  rt2 = (acmx / rt1) * acmn - (b / rt1) * b; }
    else               { rt1 = 0.5f * rt; rt2 = -0.5f * rt; sgn1 = 1; }
    int sgn2;
    float cs;
    if (df >= 0.f) { cs = df + rt; sgn2 = 1; } else { cs = df - rt; sgn2 = -1; }
    float acs = fabsf(cs);
    if (acs > ab) {
        float ct = -tb / cs;
        sn1 = 1.f / sqrtf(1.f + ct * ct);
        cs1 = ct * sn1;
    } else {
        if (ab == 0.f) { cs1 = 1.f; sn1 = 0.f; }
        else {
            float tn = -cs / tb;
            cs1 = 1.f / sqrtf(1.f + tn * tn);
            sn1 = tn * cs1;
        }
    }
    if (sgn1 == sgn2) { float tn = cs1; cs1 = -sn1; sn1 = tn; }
}

// ================= K4b: FC_out + geometry =================
__global__ void k_out(const float* __restrict__ fco_w, const float* __restrict__ fco_b,
                      const float* __restrict__ Kmat, const float* __restrict__ iris_r,
                      float* __restrict__ out) {
    int b = blockIdx.x;
    int tid = threadIdx.x, lane = tid & 31, wp = tid >> 5;

    __shared__ float hdd[256], raws[16];
    hdd[tid] = g_hdd[b * 256 + tid];
    __syncthreads();

    if (wp < 7) {
        const float* hl = hdd + lane * 8;
        // prefetch both rows' weights first
        float4 A[2][2];
#pragma unroll
        for (int oo = 0; oo < 2; oo++) {
            const float4* wr = (const float4*)(fco_w + (wp * 2 + oo) * 256);
            A[oo][0] = __ldg(wr + lane * 2);
            A[oo][1] = __ldg(wr + lane * 2 + 1);
        }
#pragma unroll
        for (int oo = 0; oo < 2; oo++) {
            int o = wp * 2 + oo;
            float4 a0 = A[oo][0], a1 = A[oo][1];
            float acc = a0.x * hl[0] + a0.y * hl[1] + a0.z * hl[2] + a0.w * hl[3]
                      + a1.x * hl[4] + a1.y * hl[5] + a1.z * hl[6] + a1.w * hl[7];
#pragma unroll
            for (int s = 16; s; s >>= 1) acc += __shfl_xor_sync(0xffffffffu, acc, s);
            if (lane == 0) raws[o] = acc + __ldg(fco_b + o);
        }
    }
    __syncthreads();

    if (tid < 2) {
        int e = tid;
        float t0 = raws[e*7+0], t1 = raws[e*7+1], t2 = raws[e*7+2], t3 = raws[e*7+3];
        float t4 = raws[e*7+4], t5 = raws[e*7+5], t6 = raws[e*7+6];

        float cx = t0, cy = t1;
        float ea = softplus_f(t2) + 1e-6f;
        float eb = softplus_f(t3) + 1e-6f;
        float n45 = sqrtf(t4 * t4 + t5 * t5);
        float cth = t4 / (n45 + 1e-8f);
        float sth = t5 / (n45 + 1e-8f);
        float delta = 0.3f * tanhf(t6);

        float hyp = sqrtf(cth * cth + sth * sth);
        float ct, st;
        if (hyp > 0.f) { ct = cth / hyp; st = sth / hyp; } else { ct = 1.f; st = 0.f; }

        float ia2 = 1.f / (ea * ea), ib2 = 1.f / (eb * eb);
        float A11 = ct * ct * ia2 + st * st * ib2;
        float A22 = st * st * ia2 + ct * ct * ib2;
        float A12 = ct * st * (ia2 - ib2);
        float ax = A11 * cx + A12 * cy;
        float ay = A12 * cx + A22 * cy;
        float cAc = A11 * cx * cx + 2.f * A12 * cx * cy + A22 * cy * cy;

        float Cm[3][3] = {{A11, A12, -ax}, {A12, A22, -ay}, {-ax, -ay, cAc - 1.f}};
        const float* Kb = Kmat + b * 9;

        float T[3][3], Cn[3][3];
#pragma unroll
        for (int j = 0; j < 3; j++)
#pragma unroll
            for (int l = 0; l < 3; l++)
                T[j][l] = Cm[j][0] * Kb[0 * 3 + l] + Cm[j][1] * Kb[1 * 3 + l] + Cm[j][2] * Kb[2 * 3 + l];
#pragma unroll
        for (int i = 0; i < 3; i++)
#pragma unroll
            for (int l = 0; l < 3; l++)
                Cn[i][l] = Kb[0 * 3 + i] * T[0][l] + Kb[1 * 3 + i] * T[1][l] + Kb[2 * 3 + i] * T[2][l];

        float a00 = Cn[0][0], a01 = Cn[0][1], a10 = Cn[1][0], a11 = Cn[1][1];
        float u0 = Cn[0][2], u1 = Cn[1][2];

        float det = a00 * a11 - a01 * a10;
        float mu0 = (-a11 * u0 + a01 * u1) / det;
        float mu1 = (a10 * u0 - a00 * u1) / det;

        float bsym = 0.5f * (a01 + a10);
        float rt1, rt2, cs1, sn1;
        slaev2(a00, bsym, a11, rt1, rt2, cs1, sn1);
        float ev0, ev1, v0, v1;
        if (rt1 <= rt2) { ev0 = rt1; ev1 = rt2; v0 = cs1;  v1 = sn1; }
        else            { ev0 = rt2; ev1 = rt1; v0 = -sn1; v1 = cs1; }

        float an = 1.f / sqrtf(fmaxf(ev0, 1e-12f));
        float bn_ = 1.f / sqrtf(fmaxf(ev1, 1e-12f));
        an = fmaxf(an, 1e-6f);

        float R = iris_r[b];
        float z = fminf(fmaxf(R / an, 0.5f), 1000.f);

        float nr = sqrtf(mu0 * mu0 + mu1 * mu1 + 1.f) + 1e-8f;
        float icx = (mu0 / nr) * z, icy = (mu1 / nr) * z, icz = (1.f / nr) * z;

        float ratio = fminf(fmaxf(bn_ / an, 0.f), 1.f);
        float ctl = ratio;
        float stl = sqrtf(fmaxf(1.f - ratio * ratio, 0.f));

        float kn = sqrtf(v0 * v0 + v1 * v1) + 1e-8f;
        float kx = v0 / kn, ky = v1 / kn;
        float px_ = ky * stl, py_ = -kx * stl, pz_ = ctl;
        float nn = sqrtf(px_ * px_ + py_ * py_ + pz_ * pz_) + 1e-8f;
        float Nx = px_ / nn, Ny = py_ / nn, Nz = pz_ / nn;

        float pcx = icx + delta * Nx, pcy = icy + delta * Ny, pcz = icz + delta * Nz;

        int idx = b * 2 + e;
        float* el = out + idx * 6;
        el[0] = cx; el[1] = cy; el[2] = ea; el[3] = eb; el[4] = cth; el[5] = sth;
        out[384 + idx] = delta;
        out[448 + idx * 3 + 0] = icx; out[448 + idx * 3 + 1] = icy; out[448 + idx * 3 + 2] = icz;
        out[640 + idx * 3 + 0] = Nx; out[640 + idx * 3 + 1] = Ny; out[640 + idx * 3 + 2] = Nz;
        out[832 + idx * 3 + 0] = pcx; out[832 + idx * 3 + 1] = pcy; out[832 + idx * 3 + 2] = pcz;
        out[1024 + idx] = z;
    }
}

// ================= launch =================
extern "C" void kernel_launch(void* const* d_in, const int* in_sizes, int n_in,
                              void* d_out, int out_size) {
    const float* x      = (const float*)d_in[0];
    const float* Kmat   = (const float*)d_in[1];
    const float* iris_r = (const float*)d_in[2];
    const float* ca_w1  = (const float*)d_in[3];
    const float* ca_bng = (const float*)d_in[4];
    const float* ca_bnb = (const float*)d_in[5];
    const float* ca_bnm = (const float*)d_in[6];
    const float* ca_bnv = (const float*)d_in[7];
    const float* ca_wh  = (const float*)d_in[8];
    const float* ca_ww  = (const float*)d_in[9];
    const float* fc1_w  = (const float*)d_in[10];
    const float* fc1_b  = (const float*)d_in[11];
    const float* bn1_g  = (const float*)d_in[12];
    const float* bn1_b  = (const float*)d_in[13];
    const float* bn1_m  = (const float*)d_in[14];
    const float* bn1_v  = (const float*)d_in[15];
    const float* fco_w  = (const float*)d_in[16];
    const float* fco_b  = (const float*)d_in[17];
    float* out = (float*)d_out;

    k_means<<<NB * NC, 256>>>(x);
    k_att1<<<dim3(NB, 4), 256>>>(ca_w1, ca_bng, ca_bnb, ca_bnm, ca_bnv);
    k_att2<<<dim3(NB, 8), 256>>>(ca_wh, ca_ww);
    k_pool<<<NB * NC, 256>>>(x);
    k_fc1<<<dim3(NB, 8), 256>>>(fc1_w, fc1_b, bn1_g, bn1_b, bn1_m, bn1_v);
    k_out<<<NB, 256>>>(fco_w, fco_b, Kmat, iris_r, out);
}

// round 8
// speedup vs baseline: 1.6892x; 1.6892x over previous
#include <cuda_runtime.h>
#include <math.h>

// ---------------- problem constants ----------------
#define NB 32
#define NC 256
#define NH 64
#define NW 64
// MIP=8, HID=256, OUT=14

// ---------------- scratch ----------------
__device__ float g_y0[NB * NC * 128];   // [b][c][0..63]=row means, [64..127]=col means
__device__ float g_ys[NB * 8 * 128];    // hswish(bn(w1@y0))
__device__ float g_att[NB * NC * 128];  // [b][c][0..63]=a_h, [64..127]=a_w
__device__ float g_p[NB * NC];          // pooled features
__device__ float g_hdd[NB * 256];       // FC1 activations

// ================= K1: row & column means of x (single pass) =================
// one block per (b,c); 256 threads; thread: seg = tid&15 (float4 within row),
// rsub = tid>>4 (row group); 4 iterations cover 64 rows.
__global__ void k_means(const float* __restrict__ x) {
    int bc = blockIdx.x;
    const float* xp = x + (size_t)bc * (NH * NW);
    int tid = threadIdx.x;
    int seg = tid & 15, rsub = tid >> 4;

    __shared__ float rowsum[64];
    __shared__ float cred[16][68];

    float c0 = 0.f, c1 = 0.f, c2 = 0.f, c3 = 0.f;
#pragma unroll
    for (int it = 0; it < 4; it++) {
        int row = it * 16 + rsub;
        float4 v = __ldg((const float4*)(xp + row * NW) + seg);
        float rs = v.x + v.y + v.z + v.w;
#pragma unroll
        for (int o = 8; o; o >>= 1) rs += __shfl_xor_sync(0xffffffffu, rs, o, 16);
        if (seg == 0) rowsum[row] = rs;
        c0 += v.x; c1 += v.y; c2 += v.z; c3 += v.w;
    }
    cred[rsub][4 * seg + 0] = c0;
    cred[rsub][4 * seg + 1] = c1;
    cred[rsub][4 * seg + 2] = c2;
    cred[rsub][4 * seg + 3] = c3;
    __syncthreads();

    if (tid < 64) {
        float cs = 0.f;
#pragma unroll
        for (int r = 0; r < 16; r++) cs += cred[r][tid];
        float* yo = g_y0 + (size_t)bc * 128;
        yo[tid]      = rowsum[tid] * (1.f / 64.f);  // xh (mean over W)
        yo[64 + tid] = cs * (1.f / 64.f);           // xw (mean over H)
    }
}

// ================= K2a: y = hswish(bn(w1 @ y0)) =================
// grid (NB, 8): b = blockIdx.x, m = blockIdx.y. 256 threads:
// l = tid&127, half = tid>>7 splits the c-reduction in two.
__global__ void k_att1(const float* __restrict__ ca_w1,
                       const float* __restrict__ bng, const float* __restrict__ bnb,
                       const float* __restrict__ bnm, const float* __restrict__ bnv) {
    int b = blockIdx.x, m = blockIdx.y;
    int tid = threadIdx.x;
    int l = tid & 127, half = tid >> 7;

    const float* y0b = g_y0 + (size_t)b * NC * 128;
    const float* w1m = ca_w1 + m * NC + half * 128;
    const float* yc  = y0b + (size_t)half * 128 * 128;

    float acc = 0.f;
#pragma unroll 4
    for (int c = 0; c < 128; c++)
        acc = fmaf(__ldg(w1m + c), __ldg(yc + c * 128 + l), acc);

    __shared__ float sh[128];
    if (half == 0) sh[l] = acc;
    __syncthreads();
    if (half == 1) {
        float s = sh[l] + acc;
        float sc = __ldg(bng + m) * rsqrtf(__ldg(bnv + m) + 1e-5f);
        float yb = (s - __ldg(bnm + m)) * sc + __ldg(bnb + m);
        float hs = yb * fminf(fmaxf(yb + 3.f, 0.f), 6.f) * (1.f / 6.f);
        g_ys[((size_t)b * 8 + m) * 128 + l] = hs;
    }
}

// ================= K2b: attention maps =================
// grid (NB, 8): b, cg (32-channel group). 256 threads.
__global__ void k_att2(const float* __restrict__ ca_wh, const float* __restrict__ ca_ww) {
    __shared__ float ys[8 * 128];
    int b = blockIdx.x, cg = blockIdx.y;
    int tid = threadIdx.x;

    // stage ys[b] (4 KB)
    {
        const float4* src = (const float4*)(g_ys + (size_t)b * 8 * 128);
        float4* dst = (float4*)ys;
        if (tid < 256) dst[tid] = __ldg(src + tid);
    }
    __syncthreads();

    int c = cg * 32 + (tid >> 3);
    int l0 = (tid & 7) * 16;
    bool ish = (l0 < 64);
    float wv[8];
#pragma unroll
    for (int m = 0; m < 8; m++)
        wv[m] = ish ? __ldg(ca_wh + c * 8 + m) : __ldg(ca_ww + c * 8 + m);

    float o16[16];
#pragma unroll
    for (int i = 0; i < 16; i++) {
        int l = l0 + i;
        float s = 0.f;
#pragma unroll
        for (int m = 0; m < 8; m++) s = fmaf(wv[m], ys[m * 128 + l], s);
        o16[i] = 1.f / (1.f + expf(-s));
    }
    float* ap = g_att + (size_t)b * NC * 128 + (size_t)c * 128 + l0;
#pragma unroll
    for (int i = 0; i < 4; i++)
        *(float4*)(ap + 4 * i) = make_float4(o16[4*i], o16[4*i+1], o16[4*i+2], o16[4*i+3]);
}

// ================= K3: attention-weighted pooling =================
__global__ void k_pool(const float* __restrict__ x) {
    int bc = blockIdx.x;
    const float* xp = x + (size_t)bc * (NH * NW);
    int tid = threadIdx.x, lane = tid & 31, wp = tid >> 5;

    __shared__ float ah[64], aw[64];
    __shared__ float ws[8];

    if (tid < 128) {
        float a = g_att[(size_t)bc * 128 + tid];
        if (tid < 64) ah[tid] = a; else aw[tid - 64] = a;
    }
    __syncthreads();

    int seg = tid & 15, rsub = tid >> 4;
    float aw0 = aw[4 * seg + 0], aw1 = aw[4 * seg + 1];
    float aw2 = aw[4 * seg + 2], aw3 = aw[4 * seg + 3];

    float acc = 0.f;
#pragma unroll
    for (int it = 0; it < 4; it++) {
        int row = it * 16 + rsub;
        float4 v = __ldg((const float4*)(xp + row * NW) + seg);
        float rdot = fmaf(v.x, aw0, fmaf(v.y, aw1, fmaf(v.z, aw2, v.w * aw3)));
        acc = fmaf(ah[row], rdot, acc);
    }
#pragma unroll
    for (int o = 16; o; o >>= 1) acc += __shfl_xor_sync(0xffffffffu, acc, o);
    if (lane == 0) ws[wp] = acc;
    __syncthreads();
    if (tid == 0) {
        float s = 0.f;
#pragma unroll
        for (int w = 0; w < 8; w++) s += ws[w];
        g_p[bc] = s * (1.f / 4096.f);
    }
}

// ================= K4a: FC1 + BN + ReLU =================
// grid (NB, 8): b, jg. warp wp handles rows j = jg*32 + wp*4 + jo (jo 0..3).
__global__ void k_fc1(const float* __restrict__ fc1_w, const float* __restrict__ fc1_b,
                      const float* __restrict__ bn1_g, const float* __restrict__ bn1_b,
                      const float* __restrict__ bn1_m, const float* __restrict__ bn1_v) {
    int b = blockIdx.x, jg = blockIdx.y;
    int tid = threadIdx.x, lane = tid & 31, wp = tid >> 5;

    __shared__ float ps[256];
    ps[tid] = g_p[b * NC + tid];
    __syncthreads();

    const float* pl = ps + lane * 8;
#pragma unroll
    for (int jo = 0; jo < 4; jo++) {
        int j = jg * 32 + wp * 4 + jo;
        const float4* wr = (const float4*)(fc1_w + j * 256);
        float4 a0 = __ldg(wr + lane * 2);
        float4 a1 = __ldg(wr + lane * 2 + 1);
        float acc = a0.x * pl[0] + a0.y * pl[1] + a0.z * pl[2] + a0.w * pl[3]
                  + a1.x * pl[4] + a1.y * pl[5] + a1.z * pl[6] + a1.w * pl[7];
#pragma unroll
        for (int o = 16; o; o >>= 1) acc += __shfl_xor_sync(0xffffffffu, acc, o);
        if (lane == 0) {
            float v = acc + __ldg(fc1_b + j);
            v = (v - __ldg(bn1_m + j)) * (__ldg(bn1_g + j) * rsqrtf(__ldg(bn1_v + j) + 1e-5f))
                + __ldg(bn1_b + j);
            g_hdd[b * 256 + j] = fmaxf(v, 0.f);
        }
    }
}

// ================= geometry helpers =================
__device__ __forceinline__ float softplus_f(float x) {
    return fmaxf(x, 0.f) + log1pf(expf(-fabsf(x)));
}

// LAPACK slaev2, bit-faithful.
__device__ void slaev2(float a, float b, float c,
                       float& rt1, float& rt2, float& cs1, float& sn1) {
    float sm = a + c, df = a - c, adf = fabsf(df);
    float tb = b + b, ab = fabsf(tb);
    float acmx, acmn;
    if (fabsf(a) > fabsf(c)) { acmx = a; acmn = c; } else { acmx = c; acmn = a; }
    float rt;
    if (adf > ab)      { float r = ab / adf; rt = adf * sqrtf(1.f + r * r); }
    else if (adf < ab) { float r = adf / ab; rt = ab * sqrtf(1.f + r * r); }
    else               { rt = ab * sqrtf(2.f); }
    int sgn1;
    if (sm < 0.f)      { rt1 = 0.5f * (sm - rt); sgn1 = -1; rt2 = (acmx / rt1) * acmn - (b / rt1) * b; }
    else if (sm > 0.f) { rt1 = 0.5f * (sm + rt); sgn1 = 1;  rt2 = (acmx / rt1) * acmn - (b / rt1) * b; }
    else               { rt1 = 0.5f * rt; rt2 = -0.5f * rt; sgn1 = 1; }
    int sgn2;
    float cs;
    if (df >= 0.f) { cs = df + rt; sgn2 = 1; } else { cs = df - rt; sgn2 = -1; }
    float acs = fabsf(cs);
    if (acs > ab) {
        float ct = -tb / cs;
        sn1 = 1.f / sqrtf(1.f + ct * ct);
        cs1 = ct * sn1;
    } else {
        if (ab == 0.f) { cs1 = 1.f; sn1 = 0.f; }
        else {
            float tn = -cs / tb;
            cs1 = 1.f / sqrtf(1.f + tn * tn);
            sn1 = tn * cs1;
        }
    }
    if (sgn1 == sgn2) { float tn = cs1; cs1 = -sn1; sn1 = tn; }
}

// ================= K4b: FC_out + geometry =================
__global__ void k_out(const float* __restrict__ fco_w, const float* __restrict__ fco_b,
                      const float* __restrict__ Kmat, const float* __restrict__ iris_r,
                      float* __restrict__ out) {
    int b = blockIdx.x;
    int tid = threadIdx.x, lane = tid & 31, wp = tid >> 5;

    __shared__ float hdd[256], raws[16];
    hdd[tid] = g_hdd[b * 256 + tid];
    __syncthreads();

    if (wp < 7) {
        const float* hl = hdd + lane * 8;
#pragma unroll
        for (int oo = 0; oo < 2; oo++) {
            int o = wp * 2 + oo;
            const float4* wr = (const float4*)(fco_w + o * 256);
            float4 a0 = __ldg(wr + lane * 2);
            float4 a1 = __ldg(wr + lane * 2 + 1);
            float acc = a0.x * hl[0] + a0.y * hl[1] + a0.z * hl[2] + a0.w * hl[3]
                      + a1.x * hl[4] + a1.y * hl[5] + a1.z * hl[6] + a1.w * hl[7];
#pragma unroll
            for (int s = 16; s; s >>= 1) acc += __shfl_xor_sync(0xffffffffu, acc, s);
            if (lane == 0) raws[o] = acc + __ldg(fco_b + o);
        }
    }
    __syncthreads();

    if (tid < 2) {
        int e = tid;
        float t0 = raws[e*7+0], t1 = raws[e*7+1], t2 = raws[e*7+2], t3 = raws[e*7+3];
        float t4 = raws[e*7+4], t5 = raws[e*7+5], t6 = raws[e*7+6];

        float cx = t0, cy = t1;
        float ea = softplus_f(t2) + 1e-6f;
        float eb = softplus_f(t3) + 1e-6f;
        float n45 = sqrtf(t4 * t4 + t5 * t5);
        float cth = t4 / (n45 + 1e-8f);
        float sth = t5 / (n45 + 1e-8f);
        float delta = 0.3f * tanhf(t6);

        float hyp = sqrtf(cth * cth + sth * sth);
        float ct, st;
        if (hyp > 0.f) { ct = cth / hyp; st = sth / hyp; } else { ct = 1.f; st = 0.f; }

        float ia2 = 1.f / (ea * ea), ib2 = 1.f / (eb * eb);
        float A11 = ct * ct * ia2 + st * st * ib2;
        float A22 = st * st * ia2 + ct * ct * ib2;
        float A12 = ct * st * (ia2 - ib2);
        float ax = A11 * cx + A12 * cy;
        float ay = A12 * cx + A22 * cy;
        float cAc = A11 * cx * cx + 2.f * A12 * cx * cy + A22 * cy * cy;

        float Cm[3][3] = {{A11, A12, -ax}, {A12, A22, -ay}, {-ax, -ay, cAc - 1.f}};
        const float* Kb = Kmat + b * 9;

        float T[3][3], Cn[3][3];
#pragma unroll
        for (int j = 0; j < 3; j++)
#pragma unroll
            for (int l = 0; l < 3; l++)
                T[j][l] = Cm[j][0] * Kb[0 * 3 + l] + Cm[j][1] * Kb[1 * 3 + l] + Cm[j][2] * Kb[2 * 3 + l];
#pragma unroll
        for (int i = 0; i < 3; i++)
#pragma unroll
            for (int l = 0; l < 3; l++)
                Cn[i][l] = Kb[0 * 3 + i] * T[0][l] + Kb[1 * 3 + i] * T[1][l] + Kb[2 * 3 + i] * T[2][l];

        float a00 = Cn[0][0], a01 = Cn[0][1], a10 = Cn[1][0], a11 = Cn[1][1];
        float u0 = Cn[0][2], u1 = Cn[1][2];

        float det = a00 * a11 - a01 * a10;
        float mu0 = (-a11 * u0 + a01 * u1) / det;
        float mu1 = (a10 * u0 - a00 * u1) / det;

        float bsym = 0.5f * (a01 + a10);
        float rt1, rt2, cs1, sn1;
        slaev2(a00, bsym, a11, rt1, rt2, cs1, sn1);
        float ev0, ev1, v0, v1;
        if (rt1 <= rt2) { ev0 = rt1; ev1 = rt2; v0 = cs1;  v1 = sn1; }
        else            { ev0 = rt2; ev1 = rt1; v0 = -sn1; v1 = cs1; }

        float an = 1.f / sqrtf(fmaxf(ev0, 1e-12f));
        float bn_ = 1.f / sqrtf(fmaxf(ev1, 1e-12f));
        an = fmaxf(an, 1e-6f);

        float R = iris_r[b];
        float z = fminf(fmaxf(R / an, 0.5f), 1000.f);

        float nr = sqrtf(mu0 * mu0 + mu1 * mu1 + 1.f) + 1e-8f;
        float icx = (mu0 / nr) * z, icy = (mu1 / nr) * z, icz = (1.f / nr) * z;

        float ratio = fminf(fmaxf(bn_ / an, 0.f), 1.f);
        float ctl = ratio;
        float stl = sqrtf(fmaxf(1.f - ratio * ratio, 0.f));

        float kn = sqrtf(v0 * v0 + v1 * v1) + 1e-8f;
        float kx = v0 / kn, ky = v1 / kn;
        float px_ = ky * stl, py_ = -kx * stl, pz_ = ctl;
        float nn = sqrtf(px_ * px_ + py_ * py_ + pz_ * pz_) + 1e-8f;
        float Nx = px_ / nn, Ny = py_ / nn, Nz = pz_ / nn;

        float pcx = icx + delta * Nx, pcy = icy + delta * Ny, pcz = icz + delta * Nz;

        int idx = b * 2 + e;
        float* el = out + idx * 6;
        el[0] = cx; el[1] = cy; el[2] = ea; el[3] = eb; el[4] = cth; el[5] = sth;
        out[384 + idx] = delta;
        out[448 + idx * 3 + 0] = icx; out[448 + idx * 3 + 1] = icy; out[448 + idx * 3 + 2] = icz;
        out[640 + idx * 3 + 0] = Nx; out[640 + idx * 3 + 1] = Ny; out[640 + idx * 3 + 2] = Nz;
        out[832 + idx * 3 + 0] = pcx; out[832 + idx * 3 + 1] = pcy; out[832 + idx * 3 + 2] = pcz;
        out[1024 + idx] = z;
    }
}

// ================= launch =================
extern "C" void kernel_launch(void* const* d_in, const int* in_sizes, int n_in,
                              void* d_out, int out_size) {
    const float* x      = (const float*)d_in[0];
    const float* Kmat   = (const float*)d_in[1];
    const float* iris_r = (const float*)d_in[2];
    const float* ca_w1  = (const float*)d_in[3];
    const float* ca_bng = (const float*)d_in[4];
    const float* ca_bnb = (const float*)d_in[5];
    const float* ca_bnm = (const float*)d_in[6];
    const float* ca_bnv = (const float*)d_in[7];
    const float* ca_wh  = (const float*)d_in[8];
    const float* ca_ww  = (const float*)d_in[9];
    const float* fc1_w  = (const float*)d_in[10];
    const float* fc1_b  = (const float*)d_in[11];
    const float* bn1_g  = (const float*)d_in[12];
    const float* bn1_b  = (const float*)d_in[13];
    const float* bn1_m  = (const float*)d_in[14];
    const float* bn1_v  = (const float*)d_in[15];
    const float* fco_w  = (const float*)d_in[16];
    const float* fco_b  = (const float*)d_in[17];
    float* out = (float*)d_out;

    k_means<<<NB * NC, 256>>>(x);
    k_att1<<<dim3(NB, 8), 256>>>(ca_w1, ca_bng, ca_bnb, ca_bnm, ca_bnv);
    k_att2<<<dim3(NB, 8), 256>>>(ca_wh, ca_ww);
    k_pool<<<NB * NC, 256>>>(x);
    k_fc1<<<dim3(NB, 8), 256>>>(fc1_w, fc1_b, bn1_g, bn1_b, bn1_m, bn1_v);
    k_out<<<NB, 256>>>(fco_w, fco_b, Kmat, iris_r, out);
}

// round 10
// speedup vs baseline: 1.8796x; 1.1127x over previous
#include <cuda_runtime.h>
#include <math.h>

// ---------------- problem constants ----------------
#define NB 32
#define NC 256
#define NH 64
#define NW 64
// MIP=8, HID=256, OUT=14

// ---------------- scratch ----------------
__device__ float g_y0[NB * NC * 128];   // [b][c][0..63]=row means, [64..127]=col means
__device__ float g_ys[NB * 8 * 128];    // hswish(bn(w1@y0))
__device__ float g_att[NB * NC * 128];  // [b][c][0..63]=a_h, [64..127]=a_w
__device__ float g_p[NB * NC];          // pooled features
__device__ float g_hdd[NB * 256];       // FC1 activations

// ================= K1: row & column means of x (single pass) =================
// one block per (b,c); 256 threads; ascending bc order.
__global__ void k_means(const float* __restrict__ x) {
    int bc = blockIdx.x;
    const float* xp = x + (size_t)bc * (NH * NW);
    int tid = threadIdx.x;
    int seg = tid & 15, rsub = tid >> 4;

    __shared__ float rowsum[64];
    __shared__ float cred[16][68];

    float c0 = 0.f, c1 = 0.f, c2 = 0.f, c3 = 0.f;
#pragma unroll
    for (int it = 0; it < 4; it++) {
        int row = it * 16 + rsub;
        float4 v = __ldg((const float4*)(xp + row * NW) + seg);
        float rs = v.x + v.y + v.z + v.w;
#pragma unroll
        for (int o = 8; o; o >>= 1) rs += __shfl_xor_sync(0xffffffffu, rs, o, 16);
        if (seg == 0) rowsum[row] = rs;
        c0 += v.x; c1 += v.y; c2 += v.z; c3 += v.w;
    }
    cred[rsub][4 * seg + 0] = c0;
    cred[rsub][4 * seg + 1] = c1;
    cred[rsub][4 * seg + 2] = c2;
    cred[rsub][4 * seg + 3] = c3;
    __syncthreads();

    if (tid < 64) {
        float cs = 0.f;
#pragma unroll
        for (int r = 0; r < 16; r++) cs += cred[r][tid];
        float* yo = g_y0 + (size_t)bc * 128;
        yo[tid]      = rowsum[tid] * (1.f / 64.f);  // xh (mean over W)
        yo[64 + tid] = cs * (1.f / 64.f);           // xw (mean over H)
    }
}

// ================= K2a: y = hswish(bn(w1 @ y0)) =================
// grid (NB, 8): b = blockIdx.x, m = blockIdx.y. 256 threads:
// l = tid&127, half = tid>>7 splits the c-reduction in two.
__global__ void k_att1(const float* __restrict__ ca_w1,
                       const float* __restrict__ bng, const float* __restrict__ bnb,
                       const float* __restrict__ bnm, const float* __restrict__ bnv) {
    int b = blockIdx.x, m = blockIdx.y;
    int tid = threadIdx.x;
    int l = tid & 127, half = tid >> 7;

    const float* y0b = g_y0 + (size_t)b * NC * 128;
    const float* w1m = ca_w1 + m * NC + half * 128;
    const float* yc  = y0b + (size_t)half * 128 * 128;

    float acc = 0.f;
#pragma unroll 4
    for (int c = 0; c < 128; c++)
        acc = fmaf(__ldg(w1m + c), __ldg(yc + c * 128 + l), acc);

    __shared__ float sh[128];
    if (half == 0) sh[l] = acc;
    __syncthreads();
    if (half == 1) {
        float s = sh[l] + acc;
        float sc = __ldg(bng + m) * rsqrtf(__ldg(bnv + m) + 1e-5f);
        float yb = (s - __ldg(bnm + m)) * sc + __ldg(bnb + m);
        float hs = yb * fminf(fmaxf(yb + 3.f, 0.f), 6.f) * (1.f / 6.f);
        g_ys[((size_t)b * 8 + m) * 128 + l] = hs;
    }
}

// ================= K2b: attention maps =================
// grid (NB, 8): b, cg (32-channel group). 256 threads.
__global__ void k_att2(const float* __restrict__ ca_wh, const float* __restrict__ ca_ww) {
    __shared__ float ys[8 * 128];
    int b = blockIdx.x, cg = blockIdx.y;
    int tid = threadIdx.x;

    // stage ys[b] (4 KB)
    {
        const float4* src = (const float4*)(g_ys + (size_t)b * 8 * 128);
        float4* dst = (float4*)ys;
        if (tid < 256) dst[tid] = __ldg(src + tid);
    }
    __syncthreads();

    int c = cg * 32 + (tid >> 3);
    int l0 = (tid & 7) * 16;
    bool ish = (l0 < 64);
    float wv[8];
#pragma unroll
    for (int m = 0; m < 8; m++)
        wv[m] = ish ? __ldg(ca_wh + c * 8 + m) : __ldg(ca_ww + c * 8 + m);

    float o16[16];
#pragma unroll
    for (int i = 0; i < 16; i++) {
        int l = l0 + i;
        float s = 0.f;
#pragma unroll
        for (int m = 0; m < 8; m++) s = fmaf(wv[m], ys[m * 128 + l], s);
        o16[i] = 1.f / (1.f + expf(-s));
    }
    float* ap = g_att + (size_t)b * NC * 128 + (size_t)c * 128 + l0;
#pragma unroll
    for (int i = 0; i < 4; i++)
        *(float4*)(ap + 4 * i) = make_float4(o16[4*i], o16[4*i+1], o16[4*i+2], o16[4*i+3]);
}

// ================= K3: attention-weighted pooling =================
// REVERSED bc order: rides the L2-resident tail of x left by k_means
// (boustrophedon across the two passes and across graph replays).
__global__ void k_pool(const float* __restrict__ x) {
    int bc = (NB * NC - 1) - blockIdx.x;
    const float* xp = x + (size_t)bc * (NH * NW);
    int tid = threadIdx.x, lane = tid & 31, wp = tid >> 5;

    __shared__ float ah[64], aw[64];
    __shared__ float ws[8];

    if (tid < 128) {
        float a = g_att[(size_t)bc * 128 + tid];
        if (tid < 64) ah[tid] = a; else aw[tid - 64] = a;
    }
    __syncthreads();

    int seg = tid & 15, rsub = tid >> 4;
    float aw0 = aw[4 * seg + 0], aw1 = aw[4 * seg + 1];
    float aw2 = aw[4 * seg + 2], aw3 = aw[4 * seg + 3];

    float acc = 0.f;
#pragma unroll
    for (int it = 0; it < 4; it++) {
        int row = it * 16 + rsub;
        float4 v = __ldg((const float4*)(xp + row * NW) + seg);
        float rdot = fmaf(v.x, aw0, fmaf(v.y, aw1, fmaf(v.z, aw2, v.w * aw3)));
        acc = fmaf(ah[row], rdot, acc);
    }
#pragma unroll
    for (int o = 16; o; o >>= 1) acc += __shfl_xor_sync(0xffffffffu, acc, o);
    if (lane == 0) ws[wp] = acc;
    __syncthreads();
    if (tid == 0) {
        float s = 0.f;
#pragma unroll
        for (int w = 0; w < 8; w++) s += ws[w];
        g_p[bc] = s * (1.f / 4096.f);
    }
}

// ================= K4a: FC1 + BN + ReLU =================
// grid (NB, 8): b, jg. warp wp handles rows j = jg*32 + wp*4 + jo (jo 0..3).
__global__ void k_fc1(const float* __restrict__ fc1_w, const float* __restrict__ fc1_b,
                      const float* __restrict__ bn1_g, const float* __restrict__ bn1_b,
                      const float* __restrict__ bn1_m, const float* __restrict__ bn1_v) {
    int b = blockIdx.x, jg = blockIdx.y;
    int tid = threadIdx.x, lane = tid & 31, wp = tid >> 5;

    __shared__ float ps[256];
    ps[tid] = g_p[b * NC + tid];
    __syncthreads();

    const float* pl = ps + lane * 8;
#pragma unroll
    for (int jo = 0; jo < 4; jo++) {
        int j = jg * 32 + wp * 4 + jo;
        const float4* wr = (const float4*)(fc1_w + j * 256);
        float4 a0 = __ldg(wr + lane * 2);
        float4 a1 = __ldg(wr + lane * 2 + 1);
        float acc = a0.x * pl[0] + a0.y * pl[1] + a0.z * pl[2] + a0.w * pl[3]
                  + a1.x * pl[4] + a1.y * pl[5] + a1.z * pl[6] + a1.w * pl[7];
#pragma unroll
        for (int o = 16; o; o >>= 1) acc += __shfl_xor_sync(0xffffffffu, acc, o);
        if (lane == 0) {
            float v = acc + __ldg(fc1_b + j);
            v = (v - __ldg(bn1_m + j)) * (__ldg(bn1_g + j) * rsqrtf(__ldg(bn1_v + j) + 1e-5f))
                + __ldg(bn1_b + j);
            g_hdd[b * 256 + j] = fmaxf(v, 0.f);
        }
    }
}

// ================= geometry helpers =================
__device__ __forceinline__ float softplus_f(float x) {
    return fmaxf(x, 0.f) + log1pf(expf(-fabsf(x)));
}

// LAPACK slaev2, bit-faithful.
__device__ void slaev2(float a, float b, float c,
                       float& rt1, float& rt2, float& cs1, float& sn1) {
    float sm = a + c, df = a - c, adf = fabsf(df);
    float tb = b + b, ab = fabsf(tb);
    float acmx, acmn;
    if (fabsf(a) > fabsf(c)) { acmx = a; acmn = c; } else { acmx = c; acmn = a; }
    float rt;
    if (adf > ab)      { float r = ab / adf; rt = adf * sqrtf(1.f + r * r); }
    else if (adf < ab) { float r = adf / ab; rt = ab * sqrtf(1.f + r * r); }
    else               { rt = ab * sqrtf(2.f); }
    int sgn1;
    if (sm < 0.f)      { rt1 = 0.5f * (sm - rt); sgn1 = -1; rt2 = (acmx / rt1) * acmn - (b / rt1) * b; }
    else if (sm > 0.f) { rt1 = 0.5f * (sm + rt); sgn1 = 1;  rt2 = (acmx / rt1) * acmn - (b / rt1) * b; }
    else               { rt1 = 0.5f * rt; rt2 = -0.5f * rt; sgn1 = 1; }
    int sgn2;
    float cs;
    if (df >= 0.f) { cs = df + rt; sgn2 = 1; } else { cs = df - rt; sgn2 = -1; }
    float acs = fabsf(cs);
    if (acs > ab) {
        float ct = -tb / cs;
        sn1 = 1.f / sqrtf(1.f + ct * ct);
        cs1 = ct * sn1;
    } else {
        if (ab == 0.f) { cs1 = 1.f; sn1 = 0.f; }
        else {
            float tn = -cs / tb;
            cs1 = 1.f / sqrtf(1.f + tn * tn);
            sn1 = tn * cs1;
        }
    }
    if (sgn1 == sgn2) { float tn = cs1; cs1 = -sn1; sn1 = tn; }
}

// ================= K4b: FC_out + geometry =================
__global__ void k_out(const float* __restrict__ fco_w, const float* __restrict__ fco_b,
                      const float* __restrict__ Kmat, const float* __restrict__ iris_r,
                      float* __restrict__ out) {
    int b = blockIdx.x;
    int tid = threadIdx.x, lane = tid & 31, wp = tid >> 5;

    __shared__ float hdd[256], raws[16];
    hdd[tid] = g_hdd[b * 256 + tid];
    __syncthreads();

    if (wp < 7) {
        const float* hl = hdd + lane * 8;
#pragma unroll
        for (int oo = 0; oo < 2; oo++) {
            int o = wp * 2 + oo;
            const float4* wr = (const float4*)(fco_w + o * 256);
            float4 a0 = __ldg(wr + lane * 2);
            float4 a1 = __ldg(wr + lane * 2 + 1);
            float acc = a0.x * hl[0] + a0.y * hl[1] + a0.z * hl[2] + a0.w * hl[3]
                      + a1.x * hl[4] + a1.y * hl[5] + a1.z * hl[6] + a1.w * hl[7];
#pragma unroll
            for (int s = 16; s; s >>= 1) acc += __shfl_xor_sync(0xffffffffu, acc, s);
            if (lane == 0) raws[o] = acc + __ldg(fco_b + o);
        }
    }
    __syncthreads();

    if (tid < 2) {
        int e = tid;
        float t0 = raws[e*7+0], t1 = raws[e*7+1], t2 = raws[e*7+2], t3 = raws[e*7+3];
        float t4 = raws[e*7+4], t5 = raws[e*7+5], t6 = raws[e*7+6];

        float cx = t0, cy = t1;
        float ea = softplus_f(t2) + 1e-6f;
        float eb = softplus_f(t3) + 1e-6f;
        float n45 = sqrtf(t4 * t4 + t5 * t5);
        float cth = t4 / (n45 + 1e-8f);
        float sth = t5 / (n45 + 1e-8f);
        float delta = 0.3f * tanhf(t6);

        float hyp = sqrtf(cth * cth + sth * sth);
        float ct, st;
        if (hyp > 0.f) { ct = cth / hyp; st = sth / hyp; } else { ct = 1.f; st = 0.f; }

        float ia2 = 1.f / (ea * ea), ib2 = 1.f / (eb * eb);
        float A11 = ct * ct * ia2 + st * st * ib2;
        float A22 = st * st * ia2 + ct * ct * ib2;
        float A12 = ct * st * (ia2 - ib2);
        float ax = A11 * cx + A12 * cy;
        float ay = A12 * cx + A22 * cy;
        float cAc = A11 * cx * cx + 2.f * A12 * cx * cy + A22 * cy * cy;

        float Cm[3][3] = {{A11, A12, -ax}, {A12, A22, -ay}, {-ax, -ay, cAc - 1.f}};
        const float* Kb = Kmat + b * 9;

        float T[3][3], Cn[3][3];
#pragma unroll
        for (int j = 0; j < 3; j++)
#pragma unroll
            for (int l = 0; l < 3; l++)
                T[j][l] = Cm[j][0] * Kb[0 * 3 + l] + Cm[j][1] * Kb[1 * 3 + l] + Cm[j][2] * Kb[2 * 3 + l];
#pragma unroll
        for (int i = 0; i < 3; i++)
#pragma unroll
            for (int l = 0; l < 3; l++)
                Cn[i][l] = Kb[0 * 3 + i] * T[0][l] + Kb[1 * 3 + i] * T[1][l] + Kb[2 * 3 + i] * T[2][l];

        float a00 = Cn[0][0], a01 = Cn[0][1], a10 = Cn[1][0], a11 = Cn[1][1];
        float u0 = Cn[0][2], u1 = Cn[1][2];

        float det = a00 * a11 - a01 * a10;
        float mu0 = (-a11 * u0 + a01 * u1) / det;
        float mu1 = (a10 * u0 - a00 * u1) / det;

        float bsym = 0.5f * (a01 + a10);
        float rt1, rt2, cs1, sn1;
        slaev2(a00, bsym, a11, rt1, rt2, cs1, sn1);
        float ev0, ev1, v0, v1;
        if (rt1 <= rt2) { ev0 = rt1; ev1 = rt2; v0 = cs1;  v1 = sn1; }
        else            { ev0 = rt2; ev1 = rt1; v0 = -sn1; v1 = cs1; }

        float an = 1.f / sqrtf(fmaxf(ev0, 1e-12f));
        float bn_ = 1.f / sqrtf(fmaxf(ev1, 1e-12f));
        an = fmaxf(an, 1e-6f);

        float R = iris_r[b];
        float z = fminf(fmaxf(R / an, 0.5f), 1000.f);

        float nr = sqrtf(mu0 * mu0 + mu1 * mu1 + 1.f) + 1e-8f;
        float icx = (mu0 / nr) * z, icy = (mu1 / nr) * z, icz = (1.f / nr) * z;

        float ratio = fminf(fmaxf(bn_ / an, 0.f), 1.f);
        float ctl = ratio;
        float stl = sqrtf(fmaxf(1.f - ratio * ratio, 0.f));

        float kn = sqrtf(v0 * v0 + v1 * v1) + 1e-8f;
        float kx = v0 / kn, ky = v1 / kn;
        float px_ = ky * stl, py_ = -kx * stl, pz_ = ctl;
        float nn = sqrtf(px_ * px_ + py_ * py_ + pz_ * pz_) + 1e-8f;
        float Nx = px_ / nn, Ny = py_ / nn, Nz = pz_ / nn;

        float pcx = icx + delta * Nx, pcy = icy + delta * Ny, pcz = icz + delta * Nz;

        int idx = b * 2 + e;
        float* el = out + idx * 6;
        el[0] = cx; el[1] = cy; el[2] = ea; el[3] = eb; el[4] = cth; el[5] = sth;
        out[384 + idx] = delta;
        out[448 + idx * 3 + 0] = icx; out[448 + idx * 3 + 1] = icy; out[448 + idx * 3 + 2] = icz;
        out[640 + idx * 3 + 0] = Nx; out[640 + idx * 3 + 1] = Ny; out[640 + idx * 3 + 2] = Nz;
        out[832 + idx * 3 + 0] = pcx; out[832 + idx * 3 + 1] = pcy; out[832 + idx * 3 + 2] = pcz;
        out[1024 + idx] = z;
    }
}

// ================= launch =================
extern "C" void kernel_launch(void* const* d_in, const int* in_sizes, int n_in,
                              void* d_out, int out_size) {
    const float* x      = (const float*)d_in[0];
    const float* Kmat   = (const float*)d_in[1];
    const float* iris_r = (const float*)d_in[2];
    const float* ca_w1  = (const float*)d_in[3];
    const float* ca_bng = (const float*)d_in[4];
    const float* ca_bnb = (const float*)d_in[5];
    const float* ca_bnm = (const float*)d_in[6];
    const float* ca_bnv = (const float*)d_in[7];
    const float* ca_wh  = (const float*)d_in[8];
    const float* ca_ww  = (const float*)d_in[9];
    const float* fc1_w  = (const float*)d_in[10];
    const float* fc1_b  = (const float*)d_in[11];
    const float* bn1_g  = (const float*)d_in[12];
    const float* bn1_b  = (const float*)d_in[13];
    const float* bn1_m  = (const float*)d_in[14];
    const float* bn1_v  = (const float*)d_in[15];
    const float* fco_w  = (const float*)d_in[16];
    const float* fco_b  = (const float*)d_in[17];
    float* out = (float*)d_out;

    k_means<<<NB * NC, 256>>>(x);
    k_att1<<<dim3(NB, 8), 256>>>(ca_w1, ca_bng, ca_bnb, ca_bnm, ca_bnv);
    k_att2<<<dim3(NB, 8), 256>>>(ca_wh, ca_ww);
    k_pool<<<NB * NC, 256>>>(x);
    k_fc1<<<dim3(NB, 8), 256>>>(fc1_w, fc1_b, bn1_g, bn1_b, bn1_m, bn1_v);
    k_out<<<NB, 256>>>(fco_w, fco_b, Kmat, iris_r, out);
}